// round 3
// baseline (speedup 1.0000x reference)
#include <cuda_runtime.h>
#include <cstdint>

#define FULLMASK 0xffffffffu
constexpr int Bn = 256;
constexpr int Cn = 40;
constexpr int NSW_BIG   = 8;
constexpr int NSW_SMALL = 10;
constexpr float ETA     = 1.0f;
constexpr float EPS_BN  = 1e-5f;
constexpr float EIG_EPS = 1e-6f;

// ---------------- device scratch (static allocation is allowed) ----------------
__device__ float g_BM [Cn*1024];
__device__ float g_S  [Cn*1024];   // batch_mean^{-1/2}
__device__ float g_Q  [Cn*1024];   // batch_mean^{1/2}
__device__ float g_BM2[Cn*1024];   // updated batch mean (post Karcher)
__device__ float g_RM [Cn*1024];   // interpolated running mean
__device__ float g_AIS[Cn*1024];   // rm^{-1/2}
__device__ float g_MSQ[Cn*1024];   // rm^{(1-t)/2}
__device__ float g_GT [Cn*1024];   // mean tangent
__device__ float g_MSL2[Cn];
__device__ float g_SCALE[Cn];
__device__ float g_SL2[Bn*Cn];
__device__ float g_XT[(size_t)Bn*Cn*1024];   // 41.9 MB tangent scratch

// ---------------- warp helpers ----------------
__device__ __forceinline__ float warp_sum(float v){
#pragma unroll
  for(int o=16;o>0;o>>=1) v += __shfl_xor_sync(FULLMASK, v, o);
  return v;
}

// out = A*B ; matrices stored column-per-lane (lane j holds column j in 32 regs).
// sh: 32*33 float scratch private to this warp. out must not alias a or b.
__device__ __forceinline__ void mm32(float* out, const float* a, const float* b,
                                     float* sh, int lane){
  __syncwarp();
#pragma unroll
  for(int i=0;i<32;i++) sh[i*33+lane] = b[i];
  __syncwarp();
#pragma unroll
  for(int i=0;i<32;i++) out[i] = 0.f;
#pragma unroll 4
  for(int k=0;k<32;k++){
    float bk = sh[k*33+lane];              // B[k][lane]
#pragma unroll
    for(int i=0;i<32;i++)
      out[i] = fmaf(__shfl_sync(FULLMASK, a[i], k), bk, out[i]);
  }
}

// out = V diag(d) V^T ; d is this lane's eigen-function value (for its column).
__device__ __forceinline__ void symf32(float* out, const float* v, float d,
                                       float* sh, int lane){
  __syncwarp();
#pragma unroll
  for(int i=0;i<32;i++) sh[i*33+lane] = v[i];
  __syncwarp();
#pragma unroll
  for(int i=0;i<32;i++) out[i] = 0.f;
#pragma unroll 4
  for(int k=0;k<32;k++){
    float coef = sh[lane*33+k] * __shfl_sync(FULLMASK, d, k); // V[lane][k]*d_k
#pragma unroll
    for(int i=0;i<32;i++)
      out[i] = fmaf(__shfl_sync(FULLMASK, v[i], k), coef, out[i]);
  }
}

// out = G*G^T
__device__ __forceinline__ void ggt32(float* out, const float* g,
                                      float* sh, int lane){
  __syncwarp();
#pragma unroll
  for(int i=0;i<32;i++) sh[i*33+lane] = g[i];
  __syncwarp();
#pragma unroll
  for(int i=0;i<32;i++) out[i] = 0.f;
#pragma unroll 4
  for(int k=0;k<32;k++){
    float gk = sh[lane*33+k];              // G[lane][k]
#pragma unroll
    for(int i=0;i<32;i++)
      out[i] = fmaf(__shfl_sync(FULLMASK, g[i], k), gk, out[i]);
  }
}

// One-sided Jacobi eigendecomposition for an SPD 32x32 matrix.
// On entry: a = columns of A (lane j holds column j).
// On exit : v = eigenvector columns, return value = eigenvalue of this column.
template<int NSWEEP>
__device__ __forceinline__ float jacobi_spd(float* a, float* v, int lane){
#pragma unroll
  for(int i=0;i<32;i++) v[i] = (i==lane) ? 1.f : 0.f;
#pragma unroll 1
  for(int sw=0; sw<NSWEEP; ++sw){
#pragma unroll 1
    for(int r=1;r<32;r++){
      float b[32];
#pragma unroll
      for(int i=0;i<32;i++) b[i] = __shfl_xor_sync(FULLMASK, a[i], r);
      float alpha=0.f, gamma=0.f;
#pragma unroll
      for(int i=0;i<32;i++){
        alpha = fmaf(a[i],a[i],alpha);
        gamma = fmaf(a[i],b[i],gamma);
      }
      float beta = __shfl_xor_sync(FULLMASK, alpha, r);
      bool isp = lane < (lane ^ r);
      float app = isp ? alpha : beta;
      float aqq = isp ? beta  : alpha;
      bool skip = !(gamma*gamma > 1e-28f*app*aqq);
      float gs   = skip ? 1.f : gamma;
      float zeta = (aqq - app) / (2.f*gs);
      float t = copysignf(1.f, zeta) / (fabsf(zeta) + sqrtf(fmaf(zeta,zeta,1.f)));
      float c = rsqrtf(fmaf(t,t,1.f));
      float s = c*t;
      if(skip){ c = 1.f; s = 0.f; }
      float se = isp ? -s : s;
#pragma unroll
      for(int i=0;i<32;i++) a[i] = fmaf(se, b[i], c*a[i]);
#pragma unroll
      for(int i=0;i<32;i++){
        float vb = __shfl_xor_sync(FULLMASK, v[i], r);
        v[i] = fmaf(se, vb, c*v[i]);
      }
    }
  }
  float n2 = 0.f;
#pragma unroll
  for(int i=0;i<32;i++) n2 = fmaf(a[i],a[i],n2);
  return sqrtf(n2);  // singular value == eigenvalue for SPD
}

// ================= kernels =================

__global__ void k_mean(const float* __restrict__ X){
  int idx = blockIdx.x*blockDim.x + threadIdx.x;
  if(idx >= Cn*1024) return;
  float acc = 0.f;
  for(int b=0;b<Bn;b++) acc += X[(size_t)b*(Cn*1024) + idx];
  g_BM[idx] = acc * (1.f/Bn);
}

__global__ __launch_bounds__(32) void k_phaseB(){
  __shared__ float sh[33*32];
  int c = blockIdx.x, lane = threadIdx.x;
  float a[32], v[32], o[32];
#pragma unroll
  for(int i=0;i<32;i++) a[i] = g_BM[c*1024 + i*32 + lane];
  float lam = jacobi_spd<NSW_SMALL>(a, v, lane);
  float wc = fmaxf(lam, EIG_EPS);
  float sq = sqrtf(wc);
  symf32(o, v, sq, sh, lane);
#pragma unroll
  for(int i=0;i<32;i++) g_Q[c*1024+i*32+lane] = o[i];
  symf32(o, v, 1.f/sq, sh, lane);
#pragma unroll
  for(int i=0;i<32;i++) g_S[c*1024+i*32+lane] = o[i];
}

constexpr int WPB = 8;

// per (b,c): Y = S X S; eigh(Y); XT = V log(l) V^T ; store XT, sum(log^2 l)
__global__ __launch_bounds__(WPB*32) void k_phaseC(const float* __restrict__ X){
  __shared__ float shall[WPB][33*32];
  int warp = threadIdx.x >> 5, lane = threadIdx.x & 31;
  int task = blockIdx.x*WPB + warp;
  float* sh = shall[warp];
  int c = task % Cn;
  const float* xin = X + (size_t)task*1024;
  float x[32], s[32], t1[32], y[32], v[32];
#pragma unroll
  for(int i=0;i<32;i++) x[i] = xin[i*32+lane];
#pragma unroll
  for(int i=0;i<32;i++) s[i] = g_S[c*1024+i*32+lane];
  mm32(t1, s, x, sh, lane);     // S*X
  mm32(y, t1, s, sh, lane);     // (S*X)*S
  float lam = jacobi_spd<NSW_BIG>(y, v, lane);
  float lg  = logf(fmaxf(lam, EIG_EPS));
  float sl2 = warp_sum(lg*lg);
  if(lane==0) g_SL2[task] = sl2;
  float xt[32];
  symf32(xt, v, lg, sh, lane);
  float* op = g_XT + (size_t)task*1024;
#pragma unroll
  for(int i=0;i<32;i++) op[i*32+lane] = xt[i];
}

__global__ void k_reduce(){
  int idx = blockIdx.x*blockDim.x + threadIdx.x;
  if(idx >= Cn*1024) return;
  float acc = 0.f;
  for(int b=0;b<Bn;b++) acc += g_XT[(size_t)b*(Cn*1024) + idx];
  g_GT[idx] = acc * (1.f/Bn);
  if(idx < Cn){
    float a2 = 0.f;
    for(int b=0;b<Bn;b++) a2 += g_SL2[b*Cn + idx];
    g_MSL2[idx] = a2 * (1.f/Bn);
  }
}

// BM2 = Q * expm(GT) * Q   (GT indefinite -> diagonal shift before Jacobi)
__global__ __launch_bounds__(32) void k_D1(){
  __shared__ float sh[33*32];
  int c = blockIdx.x, lane = threadIdx.x;
  float a[32], v[32], eg[32], q[32], t[32];
  float f2 = 0.f;
#pragma unroll
  for(int i=0;i<32;i++){ a[i] = g_GT[c*1024+i*32+lane]; f2 = fmaf(a[i],a[i],f2); }
  f2 = warp_sum(f2);
  float shift = sqrtf(f2) + 1.f;
#pragma unroll
  for(int i=0;i<32;i++) a[i] += (i==lane) ? shift : 0.f;
  float lam = jacobi_spd<NSW_SMALL>(a, v, lane) - shift;
  symf32(eg, v, expf(lam), sh, lane);
#pragma unroll
  for(int i=0;i<32;i++) q[i] = g_Q[c*1024+i*32+lane];
  mm32(t, q, eg, sh, lane);
  mm32(eg, t, q, sh, lane);
#pragma unroll
  for(int i=0;i<32;i++) g_BM2[c*1024+i*32+lane] = eg[i];
}

// rm = geodesic(running_mean, BM2, ETA)
__global__ __launch_bounds__(32) void k_D2(const float* __restrict__ rmean){
  __shared__ float sh[33*32];
  int c = blockIdx.x, lane = threadIdx.x;
  float a[32], v[32], asq[32], ais[32], t[32], mi[32];
#pragma unroll
  for(int i=0;i<32;i++) a[i] = rmean[c*1024+i*32+lane];
  float mu  = jacobi_spd<NSW_SMALL>(a, v, lane);
  float muc = fmaxf(mu, EIG_EPS);
  symf32(asq, v, sqrtf(muc), sh, lane);
  symf32(ais, v, 1.f/sqrtf(muc), sh, lane);
#pragma unroll
  for(int i=0;i<32;i++) a[i] = g_BM2[c*1024+i*32+lane];
  mm32(t,  ais, a,   sh, lane);
  mm32(mi, t,   ais, sh, lane);
  float lm  = jacobi_spd<NSW_SMALL>(mi, v, lane);
  float lme = expf(ETA * logf(fmaxf(lm, EIG_EPS)));   // eigen^ETA
  symf32(t, v, lme, sh, lane);
  mm32(a, asq, t,   sh, lane);
  mm32(t, a,   asq, sh, lane);
#pragma unroll
  for(int i=0;i<32;i++) g_RM[c*1024+i*32+lane] = t[i];
}

// GT_rm = logm(S rm S); batch_var; scale
__global__ __launch_bounds__(32) void k_D3(const float* __restrict__ std_,
                                           const float* __restrict__ rvar){
  __shared__ float sh[33*32];
  int c = blockIdx.x, lane = threadIdx.x;
  float s[32], rm[32], t[32], p[32], v[32], gtrm[32];
#pragma unroll
  for(int i=0;i<32;i++) s[i]  = g_S [c*1024+i*32+lane];
#pragma unroll
  for(int i=0;i<32;i++) rm[i] = g_RM[c*1024+i*32+lane];
  mm32(t, s, rm, sh, lane);
  mm32(p, t, s,  sh, lane);
  float lp  = jacobi_spd<NSW_SMALL>(p, v, lane);
  float lpl = logf(fmaxf(lp, EIG_EPS));
  symf32(gtrm, v, lpl, sh, lane);
  float dot=0.f, nrm=0.f;
#pragma unroll
  for(int i=0;i<32;i++){
    float g = g_GT[c*1024+i*32+lane];
    dot = fmaf(g, gtrm[i], dot);
    nrm = fmaf(gtrm[i], gtrm[i], nrm);
  }
  dot = warp_sum(dot); nrm = warp_sum(nrm);
  // mean_b ||XT_b - GT_rm||^2 = mean||XT||^2 - 2<GT,GT_rm> + ||GT_rm||^2
  float bv = g_MSL2[c] - 2.f*dot + nrm;
  float rv = (1.f - ETA)*rvar[c] + ETA*bv;
  float sc = std_[c] / sqrtf(rv + EPS_BN);
  if(lane==0) g_SCALE[c] = sc;
}

// eigh(rm) -> rm^{-1/2} and rm^{(1-t)/2}
__global__ __launch_bounds__(32) void k_D4(const float* __restrict__ pt){
  __shared__ float sh[33*32];
  int c = blockIdx.x, lane = threadIdx.x;
  float a[32], v[32], o[32];
#pragma unroll
  for(int i=0;i<32;i++) a[i] = g_RM[c*1024+i*32+lane];
  float mu  = jacobi_spd<NSW_SMALL>(a, v, lane);
  float muc = fmaxf(mu, EIG_EPS);
  float tpar = pt[0];
  symf32(o, v, 1.f/sqrtf(muc), sh, lane);
#pragma unroll
  for(int i=0;i<32;i++) g_AIS[c*1024+i*32+lane] = o[i];
  float me = expf(0.5f*(1.f - tpar)*logf(muc));
  symf32(o, v, me, sh, lane);
#pragma unroll
  for(int i=0;i<32;i++) g_MSQ[c*1024+i*32+lane] = o[i];
}

// per (b,c): Z = A X A; eigh(Z); Xn = (Msq V diag(l^{s/2})) (same)^T
__global__ __launch_bounds__(WPB*32) void k_phaseF(const float* __restrict__ X,
                                                   float* __restrict__ out){
  __shared__ float shall[WPB][33*32];
  int warp = threadIdx.x >> 5, lane = threadIdx.x & 31;
  int task = blockIdx.x*WPB + warp;
  float* sh = shall[warp];
  int c = task % Cn;
  float x[32], a[32], t1[32], z[32], v[32];
#pragma unroll
  for(int i=0;i<32;i++) x[i] = X[(size_t)task*1024 + i*32 + lane];
#pragma unroll
  for(int i=0;i<32;i++) a[i] = g_AIS[c*1024+i*32+lane];
  mm32(t1, a,  x, sh, lane);
  mm32(z,  t1, a, sh, lane);
  float lam = jacobi_spd<NSW_BIG>(z, v, lane);
  float sc  = g_SCALE[c];
  float d   = expf(sc * logf(fmaxf(lam, EIG_EPS)));  // lambda^s
  float m[32], g[32];
#pragma unroll
  for(int i=0;i<32;i++) m[i] = g_MSQ[c*1024+i*32+lane];
  mm32(g, m, v, sh, lane);           // Msq * V
  float sd = sqrtf(d);
#pragma unroll
  for(int i=0;i<32;i++) g[i] *= sd;  // scale columns by sqrt(d)
  float xn[32];
  ggt32(xn, g, sh, lane);            // G G^T = Msq V diag(d) V^T Msq
  float* op = out + (size_t)task*1024;
#pragma unroll
  for(int i=0;i<32;i++) op[i*32+lane] = xn[i];
}

// ================= launcher =================
extern "C" void kernel_launch(void* const* d_in, const int* in_sizes, int n_in,
                              void* d_out, int out_size){
  const float* X     = (const float*)d_in[0];
  const float* std_  = (const float*)d_in[1];
  const float* rmean = (const float*)d_in[2];
  const float* rvar  = (const float*)d_in[3];
  const float* pt    = (const float*)d_in[4];
  float* out = (float*)d_out;

  k_mean  <<<(Cn*1024 + 255)/256, 256>>>(X);
  k_phaseB<<<Cn, 32>>>();
  k_phaseC<<<(Bn*Cn)/WPB, WPB*32>>>(X);
  k_reduce<<<(Cn*1024 + 255)/256, 256>>>();
  k_D1    <<<Cn, 32>>>();
  k_D2    <<<Cn, 32>>>(rmean);
  k_D3    <<<Cn, 32>>>(std_, rvar);
  k_D4    <<<Cn, 32>>>(pt);
  k_phaseF<<<(Bn*Cn)/WPB, WPB*32>>>(X, out);
}

// round 5
// speedup vs baseline: 1.7331x; 1.7331x over previous
#include <cuda_runtime.h>
#include <cstdint>

#define FULLMASK 0xffffffffu
constexpr int Bn = 256;
constexpr int Cn = 40;
constexpr int MAXSW_BIG   = 10;
constexpr int MAXSW_SMALL = 12;
constexpr float EPS_BN  = 1e-5f;
constexpr float EIG_EPS = 1e-6f;
constexpr int WPB = 8;
// per-warp smem: A panel (36*32 floats, float4-aligned rows) + B panel (32*32)
constexpr int SH_PER_WARP = 36*32 + 32*32;   // 2176 floats
constexpr int SMEM_BYTES  = WPB * SH_PER_WARP * 4;

// ---------------- device scratch ----------------
__device__ __align__(16) float g_BM [Cn*1024];
__device__ __align__(16) float g_S  [Cn*1024];   // BM^{-1/2}
__device__ __align__(16) float g_Q  [Cn*1024];   // BM^{1/2}
__device__ __align__(16) float g_AIS[Cn*1024];   // BM2^{-1/2}
__device__ __align__(16) float g_MSQ[Cn*1024];   // BM2^{(1-t)/2}
__device__ __align__(16) float g_GT [Cn*1024];
__device__ float g_SCALE[Cn];
__device__ float g_SL2[Bn*Cn];
__device__ __align__(16) float g_XT[(size_t)Bn*Cn*1024];   // 41.9 MB
__device__ float4 g_P[8*Cn*256];

// ---------------- helpers ----------------
__device__ __forceinline__ float warp_sum(float v){
#pragma unroll
  for(int o=16;o>0;o>>=1) v += __shfl_xor_sync(FULLMASK, v, o);
  return v;
}

__device__ __forceinline__ unsigned long long pk2(float lo, float hi){
  unsigned long long r; asm("mov.b64 %0, {%1,%2};" : "=l"(r) : "f"(lo), "f"(hi)); return r;
}
__device__ __forceinline__ void upk2(float& lo, float& hi, unsigned long long v){
  asm("mov.b64 {%0,%1}, %2;" : "=f"(lo), "=f"(hi) : "l"(v));
}
__device__ __forceinline__ unsigned long long ffma2(unsigned long long a,
                                                    unsigned long long b,
                                                    unsigned long long c){
  unsigned long long d;
  asm("fma.rn.f32x2 %0, %1, %2, %3;" : "=l"(d) : "l"(a), "l"(b), "l"(c));
  return d;
}

// out = A*B, column-per-lane (lane j holds column j). out may alias a or b.
__device__ __forceinline__ void mm32(float* out, const float* a, const float* b,
                                     float* sh, int lane){
  float* shA = sh;            // A col-major: A[i][k] at shA[k*36+i]
  float* shB = sh + 36*32;    // B row-major: B[k][j] at shB[k*32+j]
  __syncwarp();
  {
    float4* dst = reinterpret_cast<float4*>(shA + lane*36);
#pragma unroll
    for(int u=0;u<8;u++) dst[u] = make_float4(a[4*u],a[4*u+1],a[4*u+2],a[4*u+3]);
  }
#pragma unroll
  for(int i=0;i<32;i++) shB[i*32+lane] = b[i];
  __syncwarp();
  unsigned long long acc[16];
#pragma unroll
  for(int p=0;p<16;p++) acc[p] = 0ull;
#pragma unroll 2
  for(int k=0;k<32;k++){
    float bk = shB[k*32+lane];
    unsigned long long bb = pk2(bk, bk);
    const float4* col = reinterpret_cast<const float4*>(shA + k*36);
#pragma unroll
    for(int u=0;u<8;u++){
      float4 f = col[u];
      acc[2*u]   = ffma2(pk2(f.x, f.y), bb, acc[2*u]);
      acc[2*u+1] = ffma2(pk2(f.z, f.w), bb, acc[2*u+1]);
    }
  }
#pragma unroll
  for(int p=0;p<16;p++) upk2(out[2*p], out[2*p+1], acc[p]);
  __syncwarp();
}

// dst = rows of src (columns of src^T)
__device__ __forceinline__ void transp32(float* dst, const float* src,
                                         float* sh, int lane){
  __syncwarp();
#pragma unroll
  for(int i=0;i<32;i++) sh[i*33+lane] = src[i];
  __syncwarp();
#pragma unroll
  for(int k=0;k<32;k++) dst[k] = sh[lane*33+k];
  __syncwarp();
}

// One-sided Jacobi on SPD 32x32 (column-per-lane). On exit columns of a are
// normalized eigenvectors; returns this lane's eigenvalue.
// Exact per-sweep convergence test: all pairs gamma^2 <= 1e-12 * app*aqq.
template<int MAXSWEEP>
__device__ __forceinline__ float jacobi_v(float* a, int lane){
#pragma unroll 1
  for(int sw=0; sw<MAXSWEEP; ++sw){
    // exact norm refresh (kills Hestenes drift)
    float a0=0.f,a1=0.f,a2=0.f,a3=0.f;
#pragma unroll
    for(int i=0;i<32;i+=4){
      a0=fmaf(a[i],a[i],a0);     a1=fmaf(a[i+1],a[i+1],a1);
      a2=fmaf(a[i+2],a[i+2],a2); a3=fmaf(a[i+3],a[i+3],a3);
    }
    float alpha=(a0+a1)+(a2+a3);
    bool conv = true;
#pragma unroll 1
    for(int r=1;r<32;r++){
      float b[32];
      float g0=0.f,g1=0.f,g2=0.f,g3=0.f;
#pragma unroll
      for(int i=0;i<32;i+=4){
        b[i]   = __shfl_xor_sync(FULLMASK, a[i],   r);
        b[i+1] = __shfl_xor_sync(FULLMASK, a[i+1], r);
        b[i+2] = __shfl_xor_sync(FULLMASK, a[i+2], r);
        b[i+3] = __shfl_xor_sync(FULLMASK, a[i+3], r);
        g0=fmaf(a[i],  b[i],  g0);  g1=fmaf(a[i+1],b[i+1],g1);
        g2=fmaf(a[i+2],b[i+2],g2);  g3=fmaf(a[i+3],b[i+3],g3);
      }
      float gamma=(g0+g1)+(g2+g3);
      float beta = __shfl_xor_sync(FULLMASK, alpha, r);
      bool  isp  = lane < (lane ^ r);
      float app  = isp ? alpha : beta;
      float aqq  = isp ? beta  : alpha;
      float gg   = gamma*gamma;
      float dd   = app*aqq;
      conv = conv && (gg <= 1e-12f*dd);
      bool  rot  = gg > 1e-28f*dd;
      float zeta = __fdividef(aqq - app, 2.f*gamma);
      float t    = __fdividef(copysignf(1.f, zeta),
                              fabsf(zeta) + sqrtf(fmaf(zeta,zeta,1.f)));
      t = rot ? t : 0.f;
      float c  = rsqrtf(fmaf(t,t,1.f));
      float te = isp ? -t : t;
      float se = c*te;
#pragma unroll
      for(int i=0;i<32;i++) a[i] = fmaf(se, b[i], c*a[i]);
      alpha = fmaf(te, gamma, alpha);
    }
    if(__all_sync(FULLMASK, conv)) break;
  }
  float n0=0.f,n1=0.f,n2=0.f,n3=0.f;
#pragma unroll
  for(int i=0;i<32;i+=4){
    n0=fmaf(a[i],a[i],n0);     n1=fmaf(a[i+1],a[i+1],n1);
    n2=fmaf(a[i+2],a[i+2],n2); n3=fmaf(a[i+3],a[i+3],n3);
  }
  float nn  = (n0+n1)+(n2+n3);
  float inv = rsqrtf(nn);
#pragma unroll
  for(int i=0;i<32;i++) a[i] *= inv;
  return nn*inv;   // sqrt(nn) = eigenvalue (SPD)
}

// ================= kernels =================

__global__ void k_mean1(const float4* __restrict__ X4){
  int idx = blockIdx.x*blockDim.x + threadIdx.x;
  int s   = blockIdx.y;
  float4 acc = make_float4(0.f,0.f,0.f,0.f);
  const float4* p = X4 + (size_t)(s*32)*(Cn*256) + idx;
#pragma unroll 4
  for(int b=0;b<32;b++){
    float4 v = p[(size_t)b*(Cn*256)];
    acc.x += v.x; acc.y += v.y; acc.z += v.z; acc.w += v.w;
  }
  g_P[s*(Cn*256)+idx] = acc;
}

__global__ void k_mean2(){
  int idx = blockIdx.x*blockDim.x + threadIdx.x;
  float4 acc = make_float4(0.f,0.f,0.f,0.f);
#pragma unroll
  for(int s=0;s<8;s++){
    float4 v = g_P[s*(Cn*256)+idx];
    acc.x += v.x; acc.y += v.y; acc.z += v.z; acc.w += v.w;
  }
  const float sc = 1.f/Bn;
  acc.x*=sc; acc.y*=sc; acc.z*=sc; acc.w*=sc;
  reinterpret_cast<float4*>(g_BM)[idx] = acc;
}

// eigh(BM) -> Q = BM^{1/2}, S = BM^{-1/2}
__global__ __launch_bounds__(32) void k_phaseB(){
  __shared__ __align__(16) float sh[SH_PER_WARP];
  int c = blockIdx.x, lane = threadIdx.x;
  float a[32], vr[32], w[32], o[32];
#pragma unroll
  for(int i=0;i<32;i++) a[i] = g_BM[c*1024 + i*32 + lane];
  float lam = jacobi_v<MAXSW_SMALL>(a, lane);
  float sq  = sqrtf(fmaxf(lam, EIG_EPS));
  transp32(vr, a, sh, lane);
#pragma unroll
  for(int i=0;i<32;i++) w[i] = a[i]*sq;
  mm32(o, w, vr, sh, lane);
#pragma unroll
  for(int i=0;i<32;i++) g_Q[c*1024+i*32+lane] = o[i];
  float isq = 1.f/sq;
#pragma unroll
  for(int i=0;i<32;i++) w[i] = a[i]*isq;
  mm32(o, w, vr, sh, lane);
#pragma unroll
  for(int i=0;i<32;i++) g_S[c*1024+i*32+lane] = o[i];
}

// per (b,c): Y = S X S; eigh; XT = V log(l) V^T; store XT + sum(log^2 l)
__global__ __launch_bounds__(WPB*32,2) void k_phaseC(const float* __restrict__ X){
  extern __shared__ __align__(16) float dsh[];
  int warp = threadIdx.x >> 5, lane = threadIdx.x & 31;
  float* sh = dsh + warp*SH_PER_WARP;
  int task = blockIdx.x*WPB + warp;
  int c = task % Cn;
  float x[32], s[32], t1[32];
  const float* xp = X + (size_t)task*1024;
#pragma unroll
  for(int i=0;i<32;i++) x[i] = xp[i*32+lane];
#pragma unroll
  for(int i=0;i<32;i++) s[i] = g_S[c*1024+i*32+lane];
  mm32(t1, s, x, sh, lane);
  mm32(x, t1, s, sh, lane);                 // Y = S X S
  float lam = jacobi_v<MAXSW_BIG>(x, lane); // x -> V
  float lg  = logf(fmaxf(lam, EIG_EPS));
  float sl2 = warp_sum(lg*lg);
  if(lane==0) g_SL2[task] = sl2;
  transp32(t1, x, sh, lane);                // rows of V
#pragma unroll
  for(int i=0;i<32;i++) x[i] *= lg;         // V diag(log l)
  mm32(x, x, t1, sh, lane);                 // XT
  float* op = g_XT + (size_t)task*1024;
#pragma unroll
  for(int i=0;i<32;i++) op[i*32+lane] = x[i];
}

__global__ void k_reduce1(){
  int idx = blockIdx.x*blockDim.x + threadIdx.x;
  int s   = blockIdx.y;
  float4 acc = make_float4(0.f,0.f,0.f,0.f);
  const float4* p = reinterpret_cast<const float4*>(g_XT) + (size_t)(s*32)*(Cn*256) + idx;
#pragma unroll 4
  for(int b=0;b<32;b++){
    float4 v = p[(size_t)b*(Cn*256)];
    acc.x += v.x; acc.y += v.y; acc.z += v.z; acc.w += v.w;
  }
  g_P[s*(Cn*256)+idx] = acc;
}

__global__ void k_reduce2(){
  int idx = blockIdx.x*blockDim.x + threadIdx.x;
  float4 acc = make_float4(0.f,0.f,0.f,0.f);
#pragma unroll
  for(int s=0;s<8;s++){
    float4 v = g_P[s*(Cn*256)+idx];
    acc.x += v.x; acc.y += v.y; acc.z += v.z; acc.w += v.w;
  }
  const float sc = 1.f/Bn;
  acc.x*=sc; acc.y*=sc; acc.z*=sc; acc.w*=sc;
  reinterpret_cast<float4*>(g_GT)[idx] = acc;
}

// ETA==1 collapse: rm = BM2 = Q expm(GT) Q, GT_rm = GT.
// Produces AIS = BM2^{-1/2}, MSQ = BM2^{(1-t)/2}, SCALE = std/sqrt(var+eps)
// with var = mean||XT||^2 - ||GT||^2.
__global__ __launch_bounds__(32) void k_chan(const float* __restrict__ std_,
                                             const float* __restrict__ pt){
  __shared__ __align__(16) float sh[SH_PER_WARP];
  int c = blockIdx.x, lane = threadIdx.x;
  float a[32], vr[32], w[32], t[32], q[32];
  float f2 = 0.f;
#pragma unroll
  for(int i=0;i<32;i++){ a[i] = g_GT[c*1024+i*32+lane]; f2 = fmaf(a[i],a[i],f2); }
  f2 = warp_sum(f2);                     // ||GT||_F^2
  float shift = sqrtf(f2) + 1.f;
#pragma unroll
  for(int i=0;i<32;i++) a[i] += (i==lane) ? shift : 0.f;
  float lam = jacobi_v<MAXSW_SMALL>(a, lane);
  float e = expf(lam - shift);
  transp32(vr, a, sh, lane);
#pragma unroll
  for(int i=0;i<32;i++) w[i] = a[i]*e;
  mm32(t, w, vr, sh, lane);              // expm(GT)
#pragma unroll
  for(int i=0;i<32;i++) q[i] = g_Q[c*1024+i*32+lane];
  mm32(w, q, t, sh, lane);
  mm32(t, w, q, sh, lane);               // BM2
  float lam2 = jacobi_v<MAXSW_SMALL>(t, lane);   // t -> V of BM2
  float mu   = fmaxf(lam2, EIG_EPS);
  transp32(vr, t, sh, lane);
#pragma unroll
  for(int i=0;i<32;i++) w[i] = t[i]*rsqrtf(mu);
  mm32(q, w, vr, sh, lane);
#pragma unroll
  for(int i=0;i<32;i++) g_AIS[c*1024+i*32+lane] = q[i];
  float me = expf(0.5f*(1.f - pt[0])*logf(mu));
#pragma unroll
  for(int i=0;i<32;i++) w[i] = t[i]*me;
  mm32(q, w, vr, sh, lane);
#pragma unroll
  for(int i=0;i<32;i++) g_MSQ[c*1024+i*32+lane] = q[i];
  float psl = 0.f;
  for(int b=lane;b<Bn;b+=32) psl += g_SL2[b*Cn + c];
  float msl2 = warp_sum(psl) * (1.f/Bn);
  float bv = msl2 - f2;
  float sc = std_[c] * rsqrtf(bv + EPS_BN);
  if(lane==0) g_SCALE[c] = sc;
}

// per (b,c): Z = AIS X AIS; eigh; Xn = G G^T, G = MSQ V diag(l^{s/2})
__global__ __launch_bounds__(WPB*32,2) void k_phaseF(const float* __restrict__ X,
                                                     float* __restrict__ out){
  extern __shared__ __align__(16) float dsh[];
  int warp = threadIdx.x >> 5, lane = threadIdx.x & 31;
  float* sh = dsh + warp*SH_PER_WARP;
  int task = blockIdx.x*WPB + warp;
  int c = task % Cn;
  float x[32], a[32], t1[32];
  const float* xp = X + (size_t)task*1024;
#pragma unroll
  for(int i=0;i<32;i++) x[i] = xp[i*32+lane];
#pragma unroll
  for(int i=0;i<32;i++) a[i] = g_AIS[c*1024+i*32+lane];
  mm32(t1, a, x, sh, lane);
  mm32(x, t1, a, sh, lane);                 // Z
  float lam = jacobi_v<MAXSW_BIG>(x, lane); // x -> V
  float sc  = g_SCALE[c];
  float sd  = expf(0.5f*sc * logf(fmaxf(lam, EIG_EPS)));  // lambda^{s/2}
#pragma unroll
  for(int i=0;i<32;i++) a[i] = g_MSQ[c*1024+i*32+lane];
  mm32(t1, a, x, sh, lane);                 // MSQ * V
#pragma unroll
  for(int i=0;i<32;i++) t1[i] *= sd;        // G
  transp32(x, t1, sh, lane);                // rows of G
  mm32(a, t1, x, sh, lane);                 // G G^T
  float* op = out + (size_t)task*1024;
#pragma unroll
  for(int i=0;i<32;i++) op[i*32+lane] = a[i];
}

// ================= launcher =================
extern "C" void kernel_launch(void* const* d_in, const int* in_sizes, int n_in,
                              void* d_out, int out_size){
  const float* X     = (const float*)d_in[0];
  const float* std_  = (const float*)d_in[1];
  const float* pt    = (const float*)d_in[4];
  float* out = (float*)d_out;

  cudaFuncSetAttribute(k_phaseC, cudaFuncAttributeMaxDynamicSharedMemorySize, SMEM_BYTES);
  cudaFuncSetAttribute(k_phaseF, cudaFuncAttributeMaxDynamicSharedMemorySize, SMEM_BYTES);

  k_mean1  <<<dim3(Cn, 8), 256>>>((const float4*)X);
  k_mean2  <<<Cn, 256>>>();
  k_phaseB <<<Cn, 32>>>();
  k_phaseC <<<(Bn*Cn)/WPB, WPB*32, SMEM_BYTES>>>(X);
  k_reduce1<<<dim3(Cn, 8), 256>>>();
  k_reduce2<<<Cn, 256>>>();
  k_chan   <<<Cn, 32>>>(std_, pt);
  k_phaseF <<<(Bn*Cn)/WPB, WPB*32, SMEM_BYTES>>>(X, out);
}

// round 6
// speedup vs baseline: 1.8264x; 1.0538x over previous
#include <cuda_runtime.h>
#include <cstdint>

#define FULLMASK 0xffffffffu
constexpr int Bn = 256;
constexpr int Cn = 40;
constexpr int MAXSW_BIG   = 10;
constexpr int MAXSW_SMALL = 12;
constexpr float TOL_BIG   = 1e-10f;
constexpr float TOL_SMALL = 1e-12f;
constexpr float EPS_BN  = 1e-5f;
constexpr float EIG_EPS = 1e-6f;
constexpr int WPB = 8;
// per-warp smem: A panel (36*32 floats, float4-aligned rows) + B panel (32*32)
constexpr int SH_PER_WARP = 36*32 + 32*32;   // 2176 floats
constexpr int SMEM_BYTES  = WPB * SH_PER_WARP * 4;

// ---------------- device scratch ----------------
__device__ __align__(16) float g_BM [Cn*1024];
__device__ __align__(16) float g_S  [Cn*1024];   // BM^{-1/2}
__device__ __align__(16) float g_Q  [Cn*1024];   // BM^{1/2}
__device__ __align__(16) float g_AIS[Cn*1024];   // BM2^{-1/2}
__device__ __align__(16) float g_MSQ[Cn*1024];   // BM2^{(1-t)/2}
__device__ __align__(16) float g_GT [Cn*1024];
__device__ float g_SCALE[Cn];
__device__ float g_SL2[Bn*Cn];
__device__ __align__(16) float g_XT[(size_t)Bn*Cn*1024];   // 41.9 MB
__device__ float4 g_P[8*Cn*256];

// ---------------- helpers ----------------
__device__ __forceinline__ float warp_sum(float v){
#pragma unroll
  for(int o=16;o>0;o>>=1) v += __shfl_xor_sync(FULLMASK, v, o);
  return v;
}

typedef unsigned long long u64;

__device__ __forceinline__ u64 pk2(float lo, float hi){
  u64 r; asm("mov.b64 %0, {%1,%2};" : "=l"(r) : "f"(lo), "f"(hi)); return r;
}
__device__ __forceinline__ void upk2(float& lo, float& hi, u64 v){
  asm("mov.b64 {%0,%1}, %2;" : "=f"(lo), "=f"(hi) : "l"(v));
}
__device__ __forceinline__ u64 ffma2(u64 a, u64 b, u64 c){
  u64 d; asm("fma.rn.f32x2 %0, %1, %2, %3;" : "=l"(d) : "l"(a), "l"(b), "l"(c));
  return d;
}
__device__ __forceinline__ u64 fmul2(u64 a, u64 b){
  u64 d; asm("mul.rn.f32x2 %0, %1, %2;" : "=l"(d) : "l"(a), "l"(b));
  return d;
}

__device__ __forceinline__ void packv(u64* A, const float* a){
#pragma unroll
  for(int i=0;i<16;i++) A[i] = pk2(a[2*i], a[2*i+1]);
}
__device__ __forceinline__ void unpackv(float* a, const u64* A){
#pragma unroll
  for(int i=0;i<16;i++) upk2(a[2*i], a[2*i+1], A[i]);
}

// out = A*B, column-per-lane (lane j holds column j). out may alias a or b.
__device__ __forceinline__ void mm32(float* out, const float* a, const float* b,
                                     float* sh, int lane){
  float* shA = sh;            // A col-major: A[i][k] at shA[k*36+i]
  float* shB = sh + 36*32;    // B row-major: B[k][j] at shB[k*32+j]
  __syncwarp();
  {
    float4* dst = reinterpret_cast<float4*>(shA + lane*36);
#pragma unroll
    for(int u=0;u<8;u++) dst[u] = make_float4(a[4*u],a[4*u+1],a[4*u+2],a[4*u+3]);
  }
#pragma unroll
  for(int i=0;i<32;i++) shB[i*32+lane] = b[i];
  __syncwarp();
  u64 acc[16];
#pragma unroll
  for(int p=0;p<16;p++) acc[p] = 0ull;
#pragma unroll 2
  for(int k=0;k<32;k++){
    float bk = shB[k*32+lane];
    u64 bb = pk2(bk, bk);
    const float4* col = reinterpret_cast<const float4*>(shA + k*36);
#pragma unroll
    for(int u=0;u<8;u++){
      float4 f = col[u];
      acc[2*u]   = ffma2(pk2(f.x, f.y), bb, acc[2*u]);
      acc[2*u+1] = ffma2(pk2(f.z, f.w), bb, acc[2*u+1]);
    }
  }
#pragma unroll
  for(int p=0;p<16;p++) upk2(out[2*p], out[2*p+1], acc[p]);
  __syncwarp();
}

// dst = rows of src (columns of src^T)
__device__ __forceinline__ void transp32(float* dst, const float* src,
                                         float* sh, int lane){
  __syncwarp();
#pragma unroll
  for(int i=0;i<32;i++) sh[i*33+lane] = src[i];
  __syncwarp();
#pragma unroll
  for(int k=0;k<32;k++) dst[k] = sh[lane*33+k];
  __syncwarp();
}

// One-sided Jacobi on SPD 32x32, f32x2-packed columns (lane j holds column j
// as 16 u64). On exit columns are normalized eigenvectors; returns eigenvalue.
template<int MAXSWEEP>
__device__ __forceinline__ float jacobi_v(u64* A, int lane, float tol){
#pragma unroll 1
  for(int sw=0; sw<MAXSWEEP; ++sw){
    // exact column-norm refresh each sweep
    u64 na=0ull, nb=0ull;
#pragma unroll
    for(int i=0;i<16;i+=2){ na = ffma2(A[i],A[i],na); nb = ffma2(A[i+1],A[i+1],nb); }
    float xl,xh,yl,yh; upk2(xl,xh,na); upk2(yl,yh,nb);
    float alpha = (xl+xh)+(yl+yh);
    bool conv = true;
#pragma unroll 1
    for(int r=1;r<32;r++){
      u64 Bv[16];
      u64 ga=0ull, gb=0ull;
#pragma unroll
      for(int i=0;i<16;i+=2){
        Bv[i]   = __shfl_xor_sync(FULLMASK, A[i],   r);
        Bv[i+1] = __shfl_xor_sync(FULLMASK, A[i+1], r);
        ga = ffma2(A[i],  Bv[i],  ga);
        gb = ffma2(A[i+1],Bv[i+1],gb);
      }
      upk2(xl,xh,ga); upk2(yl,yh,gb);
      float gamma = (xl+xh)+(yl+yh);
      float beta  = __shfl_xor_sync(FULLMASK, alpha, r);
      bool  isp   = lane < (lane ^ r);
      float app   = isp ? alpha : beta;
      float aqq   = isp ? beta  : alpha;
      float gg    = gamma*gamma;
      float dd    = app*aqq;
      conv = conv && (gg <= tol*dd);
      bool  rot   = gg > 1e-28f*dd;
      float zeta  = __fdividef(aqq - app, 2.f*gamma);
      float t     = __fdividef(copysignf(1.f, zeta),
                               fabsf(zeta) + sqrtf(fmaf(zeta,zeta,1.f)));
      t = rot ? t : 0.f;
      float c  = rsqrtf(fmaf(t,t,1.f));
      float te = isp ? -t : t;
      float se = c*te;
      u64 C2 = pk2(c,c), S2 = pk2(se,se);
#pragma unroll
      for(int i=0;i<16;i++) A[i] = ffma2(S2, Bv[i], fmul2(C2, A[i]));
      alpha = fmaf(te, gamma, alpha);
    }
    if(__all_sync(FULLMASK, conv)) break;
  }
  u64 na=0ull, nb=0ull;
#pragma unroll
  for(int i=0;i<16;i+=2){ na = ffma2(A[i],A[i],na); nb = ffma2(A[i+1],A[i+1],nb); }
  float xl,xh,yl,yh; upk2(xl,xh,na); upk2(yl,yh,nb);
  float nn  = (xl+xh)+(yl+yh);
  float inv = rsqrtf(nn);
  u64 I2 = pk2(inv,inv);
#pragma unroll
  for(int i=0;i<16;i++) A[i] = fmul2(I2, A[i]);
  return nn*inv;   // sqrt(nn) = eigenvalue (SPD)
}

// float-array convenience wrapper
template<int MAXSWEEP>
__device__ __forceinline__ float jacobi_vf(float* a, int lane, float tol){
  u64 A[16];
  packv(A, a);
  float lam = jacobi_v<MAXSWEEP>(A, lane, tol);
  unpackv(a, A);
  return lam;
}

// ================= kernels =================

__global__ void k_mean1(const float4* __restrict__ X4){
  int idx = blockIdx.x*blockDim.x + threadIdx.x;
  int s   = blockIdx.y;
  float4 acc = make_float4(0.f,0.f,0.f,0.f);
  const float4* p = X4 + (size_t)(s*32)*(Cn*256) + idx;
#pragma unroll 4
  for(int b=0;b<32;b++){
    float4 v = p[(size_t)b*(Cn*256)];
    acc.x += v.x; acc.y += v.y; acc.z += v.z; acc.w += v.w;
  }
  g_P[s*(Cn*256)+idx] = acc;
}

__global__ void k_mean2(){
  int idx = blockIdx.x*blockDim.x + threadIdx.x;
  float4 acc = make_float4(0.f,0.f,0.f,0.f);
#pragma unroll
  for(int s=0;s<8;s++){
    float4 v = g_P[s*(Cn*256)+idx];
    acc.x += v.x; acc.y += v.y; acc.z += v.z; acc.w += v.w;
  }
  const float sc = 1.f/Bn;
  acc.x*=sc; acc.y*=sc; acc.z*=sc; acc.w*=sc;
  reinterpret_cast<float4*>(g_BM)[idx] = acc;
}

// eigh(BM) -> Q = BM^{1/2}, S = BM^{-1/2}
__global__ __launch_bounds__(32) void k_phaseB(){
  __shared__ __align__(16) float sh[SH_PER_WARP];
  int c = blockIdx.x, lane = threadIdx.x;
  float a[32], vr[32], w[32], o[32];
#pragma unroll
  for(int i=0;i<32;i++) a[i] = g_BM[c*1024 + i*32 + lane];
  float lam = jacobi_vf<MAXSW_SMALL>(a, lane, TOL_SMALL);
  float sq  = sqrtf(fmaxf(lam, EIG_EPS));
  transp32(vr, a, sh, lane);
#pragma unroll
  for(int i=0;i<32;i++) w[i] = a[i]*sq;
  mm32(o, w, vr, sh, lane);
#pragma unroll
  for(int i=0;i<32;i++) g_Q[c*1024+i*32+lane] = o[i];
  float isq = 1.f/sq;
#pragma unroll
  for(int i=0;i<32;i++) w[i] = a[i]*isq;
  mm32(o, w, vr, sh, lane);
#pragma unroll
  for(int i=0;i<32;i++) g_S[c*1024+i*32+lane] = o[i];
}

// per (b,c): Y = S X S; eigh; XT = V log(l) V^T; store XT + sum(log^2 l)
__global__ __launch_bounds__(WPB*32,2) void k_phaseC(const float* __restrict__ X){
  extern __shared__ __align__(16) float dsh[];
  int warp = threadIdx.x >> 5, lane = threadIdx.x & 31;
  float* sh = dsh + warp*SH_PER_WARP;
  int task = blockIdx.x*WPB + warp;
  int c = task % Cn;
  float x[32], s[32], t1[32];
  const float* xp = X + (size_t)task*1024;
#pragma unroll
  for(int i=0;i<32;i++) x[i] = xp[i*32+lane];
#pragma unroll
  for(int i=0;i<32;i++) s[i] = g_S[c*1024+i*32+lane];
  mm32(t1, s, x, sh, lane);
  mm32(x, t1, s, sh, lane);                 // Y = S X S
  float lam = jacobi_vf<MAXSW_BIG>(x, lane, TOL_BIG); // x -> V
  float lg  = logf(fmaxf(lam, EIG_EPS));
  float sl2 = warp_sum(lg*lg);
  if(lane==0) g_SL2[task] = sl2;
  transp32(t1, x, sh, lane);                // rows of V
#pragma unroll
  for(int i=0;i<32;i++) x[i] *= lg;         // V diag(log l)
  mm32(x, x, t1, sh, lane);                 // XT
  float* op = g_XT + (size_t)task*1024;
#pragma unroll
  for(int i=0;i<32;i++) op[i*32+lane] = x[i];
}

__global__ void k_reduce1(){
  int idx = blockIdx.x*blockDim.x + threadIdx.x;
  int s   = blockIdx.y;
  float4 acc = make_float4(0.f,0.f,0.f,0.f);
  const float4* p = reinterpret_cast<const float4*>(g_XT) + (size_t)(s*32)*(Cn*256) + idx;
#pragma unroll 4
  for(int b=0;b<32;b++){
    float4 v = p[(size_t)b*(Cn*256)];
    acc.x += v.x; acc.y += v.y; acc.z += v.z; acc.w += v.w;
  }
  g_P[s*(Cn*256)+idx] = acc;
}

__global__ void k_reduce2(){
  int idx = blockIdx.x*blockDim.x + threadIdx.x;
  float4 acc = make_float4(0.f,0.f,0.f,0.f);
#pragma unroll
  for(int s=0;s<8;s++){
    float4 v = g_P[s*(Cn*256)+idx];
    acc.x += v.x; acc.y += v.y; acc.z += v.z; acc.w += v.w;
  }
  const float sc = 1.f/Bn;
  acc.x*=sc; acc.y*=sc; acc.z*=sc; acc.w*=sc;
  reinterpret_cast<float4*>(g_GT)[idx] = acc;
}

// ETA==1 collapse: rm = BM2 = Q expm(GT) Q, GT_rm = GT.
// AIS = BM2^{-1/2}, MSQ = BM2^{(1-t)/2}, SCALE = std/sqrt(var+eps),
// var = mean||XT||^2 - ||GT||^2.
__global__ __launch_bounds__(32) void k_chan(const float* __restrict__ std_,
                                             const float* __restrict__ pt){
  __shared__ __align__(16) float sh[SH_PER_WARP];
  int c = blockIdx.x, lane = threadIdx.x;
  float a[32], vr[32], w[32], t[32], q[32];
  float f2 = 0.f;
#pragma unroll
  for(int i=0;i<32;i++){ a[i] = g_GT[c*1024+i*32+lane]; f2 = fmaf(a[i],a[i],f2); }
  f2 = warp_sum(f2);                     // ||GT||_F^2
  float shift = sqrtf(f2) + 1.f;
#pragma unroll
  for(int i=0;i<32;i++) a[i] += (i==lane) ? shift : 0.f;
  float lam = jacobi_vf<MAXSW_SMALL>(a, lane, TOL_SMALL);
  float e = expf(lam - shift);
  transp32(vr, a, sh, lane);
#pragma unroll
  for(int i=0;i<32;i++) w[i] = a[i]*e;
  mm32(t, w, vr, sh, lane);              // expm(GT)
#pragma unroll
  for(int i=0;i<32;i++) q[i] = g_Q[c*1024+i*32+lane];
  mm32(w, q, t, sh, lane);
  mm32(t, w, q, sh, lane);               // BM2
  float lam2 = jacobi_vf<MAXSW_SMALL>(t, lane, TOL_SMALL);   // t -> V of BM2
  float mu   = fmaxf(lam2, EIG_EPS);
  transp32(vr, t, sh, lane);
#pragma unroll
  for(int i=0;i<32;i++) w[i] = t[i]*rsqrtf(mu);
  mm32(q, w, vr, sh, lane);
#pragma unroll
  for(int i=0;i<32;i++) g_AIS[c*1024+i*32+lane] = q[i];
  float me = expf(0.5f*(1.f - pt[0])*logf(mu));
#pragma unroll
  for(int i=0;i<32;i++) w[i] = t[i]*me;
  mm32(q, w, vr, sh, lane);
#pragma unroll
  for(int i=0;i<32;i++) g_MSQ[c*1024+i*32+lane] = q[i];
  float psl = 0.f;
  for(int b=lane;b<Bn;b+=32) psl += g_SL2[b*Cn + c];
  float msl2 = warp_sum(psl) * (1.f/Bn);
  float bv = msl2 - f2;
  float sc = std_[c] * rsqrtf(bv + EPS_BN);
  if(lane==0) g_SCALE[c] = sc;
}

// per (b,c): Z = AIS X AIS; eigh; Xn = G G^T, G = MSQ V diag(l^{s/2})
__global__ __launch_bounds__(WPB*32,2) void k_phaseF(const float* __restrict__ X,
                                                     float* __restrict__ out){
  extern __shared__ __align__(16) float dsh[];
  int warp = threadIdx.x >> 5, lane = threadIdx.x & 31;
  float* sh = dsh + warp*SH_PER_WARP;
  int task = blockIdx.x*WPB + warp;
  int c = task % Cn;
  float x[32], a[32], t1[32];
  const float* xp = X + (size_t)task*1024;
#pragma unroll
  for(int i=0;i<32;i++) x[i] = xp[i*32+lane];
#pragma unroll
  for(int i=0;i<32;i++) a[i] = g_AIS[c*1024+i*32+lane];
  mm32(t1, a, x, sh, lane);
  mm32(x, t1, a, sh, lane);                 // Z
  float lam = jacobi_vf<MAXSW_BIG>(x, lane, TOL_BIG); // x -> V
  float sc  = g_SCALE[c];
  float sd  = expf(0.5f*sc * logf(fmaxf(lam, EIG_EPS)));  // lambda^{s/2}
#pragma unroll
  for(int i=0;i<32;i++) a[i] = g_MSQ[c*1024+i*32+lane];
  mm32(t1, a, x, sh, lane);                 // MSQ * V
#pragma unroll
  for(int i=0;i<32;i++) t1[i] *= sd;        // G
  transp32(x, t1, sh, lane);                // rows of G
  mm32(a, t1, x, sh, lane);                 // G G^T
  float* op = out + (size_t)task*1024;
#pragma unroll
  for(int i=0;i<32;i++) op[i*32+lane] = a[i];
}

// ================= launcher =================
extern "C" void kernel_launch(void* const* d_in, const int* in_sizes, int n_in,
                              void* d_out, int out_size){
  const float* X     = (const float*)d_in[0];
  const float* std_  = (const float*)d_in[1];
  const float* pt    = (const float*)d_in[4];
  float* out = (float*)d_out;

  cudaFuncSetAttribute(k_phaseC, cudaFuncAttributeMaxDynamicSharedMemorySize, SMEM_BYTES);
  cudaFuncSetAttribute(k_phaseF, cudaFuncAttributeMaxDynamicSharedMemorySize, SMEM_BYTES);

  k_mean1  <<<dim3(Cn, 8), 256>>>((const float4*)X);
  k_mean2  <<<Cn, 256>>>();
  k_phaseB <<<Cn, 32>>>();
  k_phaseC <<<(Bn*Cn)/WPB, WPB*32, SMEM_BYTES>>>(X);
  k_reduce1<<<dim3(Cn, 8), 256>>>();
  k_reduce2<<<Cn, 256>>>();
  k_chan   <<<Cn, 32>>>(std_, pt);
  k_phaseF <<<(Bn*Cn)/WPB, WPB*32, SMEM_BYTES>>>(X, out);
}

// round 7
// speedup vs baseline: 2.4975x; 1.3674x over previous
#include <cuda_runtime.h>
#include <cstdint>

#define FULLMASK 0xffffffffu
constexpr int Bn = 256;
constexpr int Cn = 40;
constexpr int MAXSW_BIG   = 10;
constexpr int MAXSW_SMALL = 12;
constexpr float TOL_BIG   = 1e-10f;
constexpr float TOL_SMALL = 1e-12f;
constexpr float EPS_BN  = 1e-5f;
constexpr float EIG_EPS = 1e-6f;
constexpr int WPB = 8;
// per-warp smem: A panel (36*32 floats, float4 rows) + B panel (32*32)
constexpr int SH_PER_WARP = 36*32 + 32*32;   // 2176 floats
constexpr int SMEM_BYTES  = WPB * SH_PER_WARP * 4;

// ---------------- device scratch ----------------
__device__ __align__(16) float g_BM [Cn*1024];
__device__ __align__(16) float g_S  [Cn*1024];   // BM^{-1/2}
__device__ __align__(16) float g_Q  [Cn*1024];   // BM^{1/2}
__device__ __align__(16) float g_AIS[Cn*1024];   // BM2^{-1/2}
__device__ __align__(16) float g_MSQ[Cn*1024];   // BM2^{(1-t)/2}
__device__ __align__(16) float g_GT [Cn*1024];
__device__ float g_SCALE[Cn];
__device__ float g_SL2[Bn*Cn];
__device__ __align__(16) float g_XT[(size_t)Bn*Cn*1024];   // 41.9 MB
__device__ __align__(16) float g_V [(size_t)Bn*Cn*1024];   // 41.9 MB eigenvector cache
__device__ float4 g_P[8*Cn*256];

// ---------------- helpers ----------------
__device__ __forceinline__ float warp_sum(float v){
#pragma unroll
  for(int o=16;o>0;o>>=1) v += __shfl_xor_sync(FULLMASK, v, o);
  return v;
}

typedef unsigned long long u64;

__device__ __forceinline__ u64 pk2(float lo, float hi){
  u64 r; asm("mov.b64 %0, {%1,%2};" : "=l"(r) : "f"(lo), "f"(hi)); return r;
}
__device__ __forceinline__ void upk2(float& lo, float& hi, u64 v){
  asm("mov.b64 {%0,%1}, %2;" : "=f"(lo), "=f"(hi) : "l"(v));
}
__device__ __forceinline__ u64 ffma2(u64 a, u64 b, u64 c){
  u64 d; asm("fma.rn.f32x2 %0, %1, %2, %3;" : "=l"(d) : "l"(a), "l"(b), "l"(c));
  return d;
}
__device__ __forceinline__ u64 fmul2(u64 a, u64 b){
  u64 d; asm("mul.rn.f32x2 %0, %1, %2;" : "=l"(d) : "l"(a), "l"(b));
  return d;
}

__device__ __forceinline__ void packv(u64* A, const float* a){
#pragma unroll
  for(int i=0;i<16;i++) A[i] = pk2(a[2*i], a[2*i+1]);
}
__device__ __forceinline__ void unpackv(float* a, const u64* A){
#pragma unroll
  for(int i=0;i<16;i++) upk2(a[2*i], a[2*i+1], A[i]);
}

// shared mm core: consumes staged shA (col-major, stride 36) and shB (row-major)
__device__ __forceinline__ void mm_core(float* out, float* shA, float* shB, int lane){
  u64 acc[16];
#pragma unroll
  for(int p=0;p<16;p++) acc[p] = 0ull;
#pragma unroll 2
  for(int k=0;k<32;k++){
    float bk = shB[k*32+lane];
    u64 bb = pk2(bk, bk);
    const float4* col = reinterpret_cast<const float4*>(shA + k*36);
#pragma unroll
    for(int u=0;u<8;u++){
      float4 f = col[u];
      acc[2*u]   = ffma2(pk2(f.x, f.y), bb, acc[2*u]);
      acc[2*u+1] = ffma2(pk2(f.z, f.w), bb, acc[2*u+1]);
    }
  }
#pragma unroll
  for(int p=0;p<16;p++) upk2(out[2*p], out[2*p+1], acc[p]);
  __syncwarp();
}

// out = A*B, column-per-lane (lane j holds column j). out may alias a or b.
__device__ __forceinline__ void mm32(float* out, const float* a, const float* b,
                                     float* sh, int lane){
  float* shA = sh;
  float* shB = sh + 36*32;
  __syncwarp();
  {
    float4* dst = reinterpret_cast<float4*>(shA + lane*36);
#pragma unroll
    for(int u=0;u<8;u++) dst[u] = make_float4(a[4*u],a[4*u+1],a[4*u+2],a[4*u+3]);
  }
#pragma unroll
  for(int i=0;i<32;i++) shB[i*32+lane] = b[i];
  __syncwarp();
  mm_core(out, shA, shB, lane);
}

// out = A * B with B read straight from global (row-major [i*32+j], 16B aligned)
__device__ __forceinline__ void mm32_bg(float* out, const float* a,
                                        const float* __restrict__ gB,
                                        float* sh, int lane){
  float* shA = sh;
  float* shB = sh + 36*32;
  __syncwarp();
  {
    float4* dst = reinterpret_cast<float4*>(shA + lane*36);
#pragma unroll
    for(int u=0;u<8;u++) dst[u] = make_float4(a[4*u],a[4*u+1],a[4*u+2],a[4*u+3]);
  }
  {
    const float4* g4 = reinterpret_cast<const float4*>(gB);
    float4* s4 = reinterpret_cast<float4*>(shB);
#pragma unroll
    for(int u=0;u<8;u++) s4[u*32+lane] = g4[u*32+lane];
  }
  __syncwarp();
  mm_core(out, shA, shB, lane);
}

// dst = rows of src (columns of src^T)
__device__ __forceinline__ void transp32(float* dst, const float* src,
                                         float* sh, int lane){
  __syncwarp();
#pragma unroll
  for(int i=0;i<32;i++) sh[i*33+lane] = src[i];
  __syncwarp();
#pragma unroll
  for(int k=0;k<32;k++) dst[k] = sh[lane*33+k];
  __syncwarp();
}

// One-sided Jacobi on SPD 32x32, f32x2-packed columns (lane j holds column j
// as 16 u64). On exit columns are normalized eigenvectors; returns eigenvalue.
// Converged pair-steps skip the rotation update entirely.
template<int MAXSWEEP>
__device__ __forceinline__ float jacobi_v(u64* A, int lane, float tol){
#pragma unroll 1
  for(int sw=0; sw<MAXSWEEP; ++sw){
    // exact column-norm refresh each sweep
    u64 na=0ull, nb=0ull;
#pragma unroll
    for(int i=0;i<16;i+=2){ na = ffma2(A[i],A[i],na); nb = ffma2(A[i+1],A[i+1],nb); }
    float xl,xh,yl,yh; upk2(xl,xh,na); upk2(yl,yh,nb);
    float alpha = (xl+xh)+(yl+yh);
    bool conv = true;
#pragma unroll 1
    for(int r=1;r<32;r++){
      u64 Bv[16];
      u64 ga=0ull, gb=0ull;
#pragma unroll
      for(int i=0;i<16;i+=2){
        Bv[i]   = __shfl_xor_sync(FULLMASK, A[i],   r);
        Bv[i+1] = __shfl_xor_sync(FULLMASK, A[i+1], r);
        ga = ffma2(A[i],  Bv[i],  ga);
        gb = ffma2(A[i+1],Bv[i+1],gb);
      }
      upk2(xl,xh,ga); upk2(yl,yh,gb);
      float gamma = (xl+xh)+(yl+yh);
      float beta  = __shfl_xor_sync(FULLMASK, alpha, r);
      bool  isp   = lane < (lane ^ r);
      float app   = isp ? alpha : beta;
      float aqq   = isp ? beta  : alpha;
      float gg    = gamma*gamma;
      float dd    = app*aqq;
      bool stepc  = gg <= tol*dd;
      conv = conv && stepc;
      if(!__all_sync(FULLMASK, stepc)){
        float d   = aqq - app;
        float g2  = gamma + gamma;
        float h   = sqrtf(fmaf(d,d, g2*g2));
        float t   = __fdividef(g2, copysignf(fabsf(d) + h, d));
        bool  rot = gg > 1e-28f*dd;
        t = rot ? t : 0.f;
        float c  = rsqrtf(fmaf(t,t,1.f));
        float te = isp ? -t : t;
        float se = c*te;
        u64 C2 = pk2(c,c), S2 = pk2(se,se);
#pragma unroll
        for(int i=0;i<16;i++) A[i] = ffma2(S2, Bv[i], fmul2(C2, A[i]));
        alpha = fmaf(te, gamma, alpha);
      }
    }
    if(__all_sync(FULLMASK, conv)) break;
  }
  u64 na=0ull, nb=0ull;
#pragma unroll
  for(int i=0;i<16;i+=2){ na = ffma2(A[i],A[i],na); nb = ffma2(A[i+1],A[i+1],nb); }
  float xl,xh,yl,yh; upk2(xl,xh,na); upk2(yl,yh,nb);
  float nn  = (xl+xh)+(yl+yh);
  float inv = rsqrtf(nn);
  u64 I2 = pk2(inv,inv);
#pragma unroll
  for(int i=0;i<16;i++) A[i] = fmul2(I2, A[i]);
  return nn*inv;   // sqrt(nn) = eigenvalue (SPD)
}

template<int MAXSWEEP>
__device__ __forceinline__ float jacobi_vf(float* a, int lane, float tol){
  u64 A[16];
  packv(A, a);
  float lam = jacobi_v<MAXSWEEP>(A, lane, tol);
  unpackv(a, A);
  return lam;
}

// ================= kernels =================

__global__ void k_mean1(const float4* __restrict__ X4){
  int idx = blockIdx.x*blockDim.x + threadIdx.x;
  int s   = blockIdx.y;
  float4 acc = make_float4(0.f,0.f,0.f,0.f);
  const float4* p = X4 + (size_t)(s*32)*(Cn*256) + idx;
#pragma unroll 4
  for(int b=0;b<32;b++){
    float4 v = p[(size_t)b*(Cn*256)];
    acc.x += v.x; acc.y += v.y; acc.z += v.z; acc.w += v.w;
  }
  g_P[s*(Cn*256)+idx] = acc;
}

__global__ void k_mean2(){
  int idx = blockIdx.x*blockDim.x + threadIdx.x;
  float4 acc = make_float4(0.f,0.f,0.f,0.f);
#pragma unroll
  for(int s=0;s<8;s++){
    float4 v = g_P[s*(Cn*256)+idx];
    acc.x += v.x; acc.y += v.y; acc.z += v.z; acc.w += v.w;
  }
  const float sc = 1.f/Bn;
  acc.x*=sc; acc.y*=sc; acc.z*=sc; acc.w*=sc;
  reinterpret_cast<float4*>(g_BM)[idx] = acc;
}

// eigh(BM) -> Q = BM^{1/2}, S = BM^{-1/2}
__global__ __launch_bounds__(32) void k_phaseB(){
  __shared__ __align__(16) float sh[SH_PER_WARP];
  int c = blockIdx.x, lane = threadIdx.x;
  float a[32], vr[32], w[32], o[32];
#pragma unroll
  for(int i=0;i<32;i++) a[i] = g_BM[c*1024 + i*32 + lane];
  float lam = jacobi_vf<MAXSW_SMALL>(a, lane, TOL_SMALL);
  float sq  = sqrtf(fmaxf(lam, EIG_EPS));
  transp32(vr, a, sh, lane);
#pragma unroll
  for(int i=0;i<32;i++) w[i] = a[i]*sq;
  mm32(o, w, vr, sh, lane);
#pragma unroll
  for(int i=0;i<32;i++) g_Q[c*1024+i*32+lane] = o[i];
  float isq = 1.f/sq;
#pragma unroll
  for(int i=0;i<32;i++) w[i] = a[i]*isq;
  mm32(o, w, vr, sh, lane);
#pragma unroll
  for(int i=0;i<32;i++) g_S[c*1024+i*32+lane] = o[i];
}

// per (b,c): Y = S X S; eigh; cache V; XT = V log(l) V^T; store XT + sum(log^2 l)
__global__ __launch_bounds__(WPB*32,2) void k_phaseC(const float* __restrict__ X){
  extern __shared__ __align__(16) float dsh[];
  int warp = threadIdx.x >> 5, lane = threadIdx.x & 31;
  float* sh = dsh + warp*SH_PER_WARP;
  int task = blockIdx.x*WPB + warp;
  int c = task % Cn;
  float x[32], s[32];
  const float* xp = X + (size_t)task*1024;
#pragma unroll
  for(int i=0;i<32;i++) s[i] = g_S[c*1024+i*32+lane];
  mm32_bg(x, s, xp, sh, lane);              // S*X
  mm32(x, x, s, sh, lane);                  // (S X) S
  float lam = jacobi_vf<MAXSW_BIG>(x, lane, TOL_BIG); // x -> V
  float lg  = logf(fmaxf(lam, EIG_EPS));
  float sl2 = warp_sum(lg*lg);
  if(lane==0) g_SL2[task] = sl2;
  float* vp = g_V + (size_t)task*1024;
#pragma unroll
  for(int i=0;i<32;i++) vp[i*32+lane] = x[i];   // cache V for phase F
  transp32(s, x, sh, lane);                 // rows of V
#pragma unroll
  for(int i=0;i<32;i++) x[i] *= lg;         // V diag(log l)
  mm32(x, x, s, sh, lane);                  // XT
  float* op = g_XT + (size_t)task*1024;
#pragma unroll
  for(int i=0;i<32;i++) op[i*32+lane] = x[i];
}

__global__ void k_reduce1(){
  int idx = blockIdx.x*blockDim.x + threadIdx.x;
  int s   = blockIdx.y;
  float4 acc = make_float4(0.f,0.f,0.f,0.f);
  const float4* p = reinterpret_cast<const float4*>(g_XT) + (size_t)(s*32)*(Cn*256) + idx;
#pragma unroll 4
  for(int b=0;b<32;b++){
    float4 v = p[(size_t)b*(Cn*256)];
    acc.x += v.x; acc.y += v.y; acc.z += v.z; acc.w += v.w;
  }
  g_P[s*(Cn*256)+idx] = acc;
}

__global__ void k_reduce2(){
  int idx = blockIdx.x*blockDim.x + threadIdx.x;
  float4 acc = make_float4(0.f,0.f,0.f,0.f);
#pragma unroll
  for(int s=0;s<8;s++){
    float4 v = g_P[s*(Cn*256)+idx];
    acc.x += v.x; acc.y += v.y; acc.z += v.z; acc.w += v.w;
  }
  const float sc = 1.f/Bn;
  acc.x*=sc; acc.y*=sc; acc.z*=sc; acc.w*=sc;
  reinterpret_cast<float4*>(g_GT)[idx] = acc;
}

// ETA==1 collapse: rm = BM2 = Q expm(GT) Q, GT_rm = GT.
// AIS = BM2^{-1/2}, MSQ = BM2^{(1-t)/2}, SCALE = std/sqrt(var+eps),
// var = mean||XT||^2 - ||GT||^2.
__global__ __launch_bounds__(32) void k_chan(const float* __restrict__ std_,
                                             const float* __restrict__ pt){
  __shared__ __align__(16) float sh[SH_PER_WARP];
  int c = blockIdx.x, lane = threadIdx.x;
  float a[32], vr[32], w[32], t[32], q[32];
  float f2 = 0.f;
#pragma unroll
  for(int i=0;i<32;i++){ a[i] = g_GT[c*1024+i*32+lane]; f2 = fmaf(a[i],a[i],f2); }
  f2 = warp_sum(f2);                     // ||GT||_F^2
  float shift = sqrtf(f2) + 1.f;
#pragma unroll
  for(int i=0;i<32;i++) a[i] += (i==lane) ? shift : 0.f;
  float lam = jacobi_vf<MAXSW_SMALL>(a, lane, TOL_SMALL);
  float e = expf(lam - shift);
  transp32(vr, a, sh, lane);
#pragma unroll
  for(int i=0;i<32;i++) w[i] = a[i]*e;
  mm32(t, w, vr, sh, lane);              // expm(GT)
#pragma unroll
  for(int i=0;i<32;i++) q[i] = g_Q[c*1024+i*32+lane];
  mm32(w, q, t, sh, lane);
  mm32(t, w, q, sh, lane);               // BM2
  float lam2 = jacobi_vf<MAXSW_SMALL>(t, lane, TOL_SMALL);   // t -> V of BM2
  float mu   = fmaxf(lam2, EIG_EPS);
  transp32(vr, t, sh, lane);
#pragma unroll
  for(int i=0;i<32;i++) w[i] = t[i]*rsqrtf(mu);
  mm32(q, w, vr, sh, lane);
#pragma unroll
  for(int i=0;i<32;i++) g_AIS[c*1024+i*32+lane] = q[i];
  float me = expf(0.5f*(1.f - pt[0])*logf(mu));
#pragma unroll
  for(int i=0;i<32;i++) w[i] = t[i]*me;
  mm32(q, w, vr, sh, lane);
#pragma unroll
  for(int i=0;i<32;i++) g_MSQ[c*1024+i*32+lane] = q[i];
  float psl = 0.f;
  for(int b=lane;b<Bn;b+=32) psl += g_SL2[b*Cn + c];
  float msl2 = warp_sum(psl) * (1.f/Bn);
  float bv = msl2 - f2;
  float sc = std_[c] * rsqrtf(bv + EPS_BN);
  if(lane==0) g_SCALE[c] = sc;
}

// per (b,c): warm-started eigh of Z = AIS X AIS using cached V from phase C:
// W = (AIS V)^T X (AIS V) is nearly diagonal -> few sweeps.
// Xn = G G^T, G = MSQ (V Vw) diag(l^{s/2})
__global__ __launch_bounds__(WPB*32,2) void k_phaseF(const float* __restrict__ X,
                                                     float* __restrict__ out){
  extern __shared__ __align__(16) float dsh[];
  int warp = threadIdx.x >> 5, lane = threadIdx.x & 31;
  float* sh = dsh + warp*SH_PER_WARP;
  int task = blockIdx.x*WPB + warp;
  int c = task % Cn;
  float v[32], p[32], t[32], w[32];
  const float* xp = X + (size_t)task*1024;
  const float* vp = g_V + (size_t)task*1024;
#pragma unroll
  for(int i=0;i<32;i++) v[i] = vp[i*32+lane];       // V (cols)
#pragma unroll
  for(int i=0;i<32;i++) t[i] = g_AIS[c*1024+i*32+lane];
  mm32(p, t, v, sh, lane);                 // P = AIS * V
  transp32(t, p, sh, lane);                // Pt
  mm32_bg(t, t, xp, sh, lane);             // Pt * X
  mm32(w, t, p, sh, lane);                 // W = Pt X P  (near diagonal)
  float lam = jacobi_vf<MAXSW_BIG>(w, lane, TOL_BIG);  // w -> Vw
  float sc  = g_SCALE[c];
  float sd  = expf(0.5f*sc * logf(fmaxf(lam, EIG_EPS)));  // lambda^{s/2}
#pragma unroll
  for(int i=0;i<32;i++) t[i] = g_MSQ[c*1024+i*32+lane];
  mm32(v, t, v, sh, lane);                 // H = MSQ * V
  mm32(w, v, w, sh, lane);                 // G0 = H * Vw
#pragma unroll
  for(int i=0;i<32;i++) w[i] *= sd;        // G
  transp32(v, w, sh, lane);                // rows of G
  mm32(p, w, v, sh, lane);                 // G G^T
  float* op = out + (size_t)task*1024;
#pragma unroll
  for(int i=0;i<32;i++) op[i*32+lane] = p[i];
}

// ================= launcher =================
extern "C" void kernel_launch(void* const* d_in, const int* in_sizes, int n_in,
                              void* d_out, int out_size){
  const float* X     = (const float*)d_in[0];
  const float* std_  = (const float*)d_in[1];
  const float* pt    = (const float*)d_in[4];
  float* out = (float*)d_out;

  cudaFuncSetAttribute(k_phaseC, cudaFuncAttributeMaxDynamicSharedMemorySize, SMEM_BYTES);
  cudaFuncSetAttribute(k_phaseF, cudaFuncAttributeMaxDynamicSharedMemorySize, SMEM_BYTES);

  k_mean1  <<<dim3(Cn, 8), 256>>>((const float4*)X);
  k_mean2  <<<Cn, 256>>>();
  k_phaseB <<<Cn, 32>>>();
  k_phaseC <<<(Bn*Cn)/WPB, WPB*32, SMEM_BYTES>>>(X);
  k_reduce1<<<dim3(Cn, 8), 256>>>();
  k_reduce2<<<Cn, 256>>>();
  k_chan   <<<Cn, 32>>>(std_, pt);
  k_phaseF <<<(Bn*Cn)/WPB, WPB*32, SMEM_BYTES>>>(X, out);
}